// round 8
// baseline (speedup 1.0000x reference)
#include <cuda_runtime.h>
#include <cstdint>
#include <math.h>

// ---------------- problem constants ----------------
#define T_TOK 1024
#define H_DIM 2048
#define I_DIM 1408
#define N_EXP 8

// ---------------- tiling ----------------
#define BM 64             // slots per tile (smaller -> less padding waste)
#define BN 128
#define BK 32
#define NSTAGE 3
#define MAXSLOT  2560     // 2048 + 8*63 padded to 64-multiples <= 2552
#define MAXTILES 40
#define NTHREADS 256

#define SM_STRIDE 36      // floats per smem row (144 B; frag banks (4g+tg)%32 all distinct)
#define A_WORDS (BM * SM_STRIDE)                        // 2304 floats = 9 KB
#define B_WORDS (BN * SM_STRIDE)                        // 4608 floats = 18 KB
#define STAGE_WORDS (A_WORDS + B_WORDS)                 // 27 KB
#define SMEM_DYN_BYTES (NSTAGE * STAGE_WORDS * 4)       // 81 KB -> 2 blocks/SM

// ---------------- scratch ----------------
__device__ int   g_token_of_slot[MAXSLOT];
__device__ float g_slot_weight[MAXSLOT];
__device__ int   g_tile_expert[MAXTILES];
__device__ int   g_num_tiles;
__device__ float g_act[(size_t)MAXSLOT * I_DIM];   // ~14.4 MB

// ---------------- PTX helpers (baseline sm_80+; nothing 'a'-gated) ----------------
__device__ __forceinline__ uint32_t smem_u32(const void* p) {
    uint32_t a;
    asm("{ .reg .u64 t; cvta.to.shared.u64 t, %1; cvt.u32.u64 %0, t; }" : "=r"(a) : "l"(p));
    return a;
}
#define CP_ASYNC16(dst_u32, src_ptr) \
    asm volatile("cp.async.cg.shared.global [%0], [%1], 16;" :: "r"(dst_u32), "l"(src_ptr))
#define CP_COMMIT()  asm volatile("cp.async.commit_group;" ::: "memory")
#define CP_WAIT(N)   asm volatile("cp.async.wait_group %0;" :: "n"(N) : "memory")

__device__ __forceinline__ uint32_t f2tf32(float f) {
    uint32_t r;
    asm("cvt.rna.tf32.f32 %0, %1;" : "=r"(r) : "f"(f));
    return r;
}
__device__ __forceinline__ void mma_tf32(float* c, const uint32_t* a, const uint32_t* b) {
    asm volatile(
        "mma.sync.aligned.m16n8k8.row.col.f32.tf32.tf32.f32 "
        "{%0,%1,%2,%3}, {%4,%5,%6,%7}, {%8,%9}, {%0,%1,%2,%3};"
        : "+f"(c[0]), "+f"(c[1]), "+f"(c[2]), "+f"(c[3])
        : "r"(a[0]), "r"(a[1]), "r"(a[2]), "r"(a[3]), "r"(b[0]), "r"(b[1]));
}

// ============================================================
// Dummy kernels: shift ncu's "-s 5 -c 1" window onto gemm1_mma.
// ============================================================
__global__ void dummy_align_kernel() {}

// ============================================================
// Routing: softmax -> top2 -> renormalize; padded per-expert slot lists (x64).
// ============================================================
__global__ void routing_kernel(const float* __restrict__ logits) {
    __shared__ int s_cnt[N_EXP];
    __shared__ int s_cur[N_EXP];
    __shared__ int s_off[N_EXP + 1];

    const int t = threadIdx.x;
    if (t < N_EXP) { s_cnt[t] = 0; s_cur[t] = 0; }
    for (int s = t; s < MAXSLOT; s += blockDim.x) g_token_of_slot[s] = -1;
    __syncthreads();

    int e1 = 0, e2 = 0;
    float w1 = 0.f, w2 = 0.f;
    if (t < T_TOK) {
        float l[N_EXP];
#pragma unroll
        for (int e = 0; e < N_EXP; e++) l[e] = logits[t * N_EXP + e];
        float b1 = -1e30f;
#pragma unroll
        for (int e = 0; e < N_EXP; e++) if (l[e] > b1) { b1 = l[e]; e1 = e; }
        float b2 = -1e30f;
        e2 = (e1 == 0) ? 1 : 0;
#pragma unroll
        for (int e = 0; e < N_EXP; e++) if (e != e1 && l[e] > b2) { b2 = l[e]; e2 = e; }
        float p2 = expf(b2 - b1);
        w1 = 1.f / (1.f + p2);
        w2 = p2 / (1.f + p2);
        atomicAdd(&s_cnt[e1], 1);
        atomicAdd(&s_cnt[e2], 1);
    }
    __syncthreads();

    if (t == 0) {
        int off = 0;
        for (int e = 0; e < N_EXP; e++) {
            s_off[e] = off;
            int tiles = (s_cnt[e] + BM - 1) / BM;
            for (int i = 0; i < tiles; i++) g_tile_expert[off / BM + i] = e;
            off += tiles * BM;
        }
        s_off[N_EXP] = off;
        g_num_tiles = off / BM;
    }
    __syncthreads();

    if (t < T_TOK) {
        int p = atomicAdd(&s_cur[e1], 1);
        int s = s_off[e1] + p;
        g_token_of_slot[s] = t;
        g_slot_weight[s]   = w1;
        p = atomicAdd(&s_cur[e2], 1);
        s = s_off[e2] + p;
        g_token_of_slot[s] = t;
        g_slot_weight[s]   = w2;
    }
}

// ============================================================
// Fragment context + per-chunk MMA.
// 8 warps: wm = wid&1 (m-group of 32 rows), wn = wid>>1 (4 n-groups of 32 cols).
// Warp tile 32x32: mf 0..1 (16 rows), nf 0..3 (8 cols). acc[2][4][4].
// ============================================================
struct FragCtx { int wm, wn, g, tg; };

__device__ __forceinline__ void mma_chunk(const float* __restrict__ A,
                                          const float* __restrict__ B,
                                          const FragCtx& f,
                                          float acc[2][4][4]) {
#pragma unroll
    for (int ks = 0; ks < 4; ks++) {
        uint32_t af[2][4];
#pragma unroll
        for (int mf = 0; mf < 2; mf++) {
            const int row = f.wm * 32 + mf * 16 + f.g;
            const int base = row * SM_STRIDE + ks * 8 + f.tg;
            af[mf][0] = f2tf32(A[base]);
            af[mf][1] = f2tf32(A[base + 8 * SM_STRIDE]);
            af[mf][2] = f2tf32(A[base + 4]);
            af[mf][3] = f2tf32(A[base + 8 * SM_STRIDE + 4]);
        }
        uint32_t bf[4][2];
#pragma unroll
        for (int nf = 0; nf < 4; nf++) {
            const int n = f.wn * 32 + nf * 8 + f.g;
            const int base = n * SM_STRIDE + ks * 8 + f.tg;
            bf[nf][0] = f2tf32(B[base]);
            bf[nf][1] = f2tf32(B[base + 4]);
        }
#pragma unroll
        for (int mf = 0; mf < 2; mf++)
#pragma unroll
            for (int nf = 0; nf < 4; nf++)
                mma_tf32(acc[mf][nf], af[mf], bf[nf]);
    }
}

// loaders: A 64x32 (2 segs/thread), B 128x32 (4 segs/thread); 256 threads
__device__ __forceinline__ void issue_chunk(uint32_t aDst, uint32_t bDst,
                                            const float* aSrc, const float* bSrc,
                                            int kOff, int aSb, int bSb) {
#pragma unroll
    for (int i = 0; i < 2; i++)
        CP_ASYNC16(aDst + i * 16, aSrc + kOff + (aSb + i) * 4);
#pragma unroll
    for (int i = 0; i < 4; i++)
        CP_ASYNC16(bDst + i * 16, bSrc + kOff + (bSb + i) * 4);
    CP_COMMIT();
}

// ============================================================
// GEMM1 + SiLU*up. B rows interleaved gate/up. grid = (MAXTILES, I/64), 256 thr
// ============================================================
__global__ __launch_bounds__(NTHREADS)
void gemm1_mma(const float* __restrict__ x, const float* __restrict__ w13) {
    const int tile_m = blockIdx.x;
    if (tile_m >= g_num_tiles) return;
    const int e   = g_tile_expert[tile_m];
    const int nbJ = blockIdx.y * 64;

    extern __shared__ float sm[];

    const int tid = threadIdx.x;
    const int wid = tid >> 5, lid = tid & 31;
    FragCtx f = { wid & 1, wid >> 1, lid >> 2, lid & 3 };

    // A loader: row ra = tid>>2 (0..63), segs aSb..aSb+1
    const int ra  = tid >> 2;
    const int aSb = (tid & 3) * 2;
    const int tokr = g_token_of_slot[tile_m * BM + ra];
    const float* aSrc = x + (size_t)(tokr < 0 ? 0 : tokr) * H_DIM;
    // B loader: row rb = tid>>1 (0..127), segs bSb..bSb+3
    const int rb  = tid >> 1;
    const int bSb = (tid & 1) * 4;
    const int j = rb >> 1;
    const int wrow = (rb & 1) ? (I_DIM + nbJ + j) : (nbJ + j);
    const float* bSrc = w13 + ((size_t)e * 2 * I_DIM + wrow) * H_DIM;

    const uint32_t smBase = smem_u32(sm);
    uint32_t aDst[NSTAGE], bDst[NSTAGE];
#pragma unroll
    for (int s = 0; s < NSTAGE; s++) {
        aDst[s] = smBase + (s * STAGE_WORDS + ra * SM_STRIDE) * 4 + aSb * 16;
        bDst[s] = smBase + (s * STAGE_WORDS + A_WORDS + rb * SM_STRIDE) * 4 + bSb * 16;
    }

    float acc[2][4][4];
#pragma unroll
    for (int a = 0; a < 2; a++)
#pragma unroll
        for (int b = 0; b < 4; b++)
#pragma unroll
            for (int c = 0; c < 4; c++) acc[a][b][c] = 0.f;

    const int NC = H_DIM / BK;   // 64
    issue_chunk(aDst[0], bDst[0], aSrc, bSrc, 0, aSb, bSb);
    issue_chunk(aDst[1], bDst[1], aSrc, bSrc, BK, aSb, bSb);

    int stage = 0, stage2 = 2;
#pragma unroll 1
    for (int c = 0; c < NC; c++) {
        if (c + 1 < NC) CP_WAIT(1); else CP_WAIT(0);
        __syncthreads();
        if (c + 2 < NC)
            issue_chunk(aDst[stage2], bDst[stage2], aSrc, bSrc, (c + 2) * BK, aSb, bSb);
        mma_chunk(sm + stage * STAGE_WORDS, sm + stage * STAGE_WORDS + A_WORDS, f, acc);
        stage = (stage + 1 == NSTAGE) ? 0 : stage + 1;
        stage2 = (stage2 + 1 == NSTAGE) ? 0 : stage2 + 1;
    }

    // epilogue: silu(gate)*up; c-pair (even,odd) = (gate, up) of same col
#pragma unroll
    for (int mf = 0; mf < 2; mf++) {
#pragma unroll
        for (int half = 0; half < 2; half++) {
            const int slot = tile_m * BM + f.wm * 32 + mf * 16 + f.g + half * 8;
            if (g_token_of_slot[slot] >= 0) {
                float* dst = g_act + (size_t)slot * I_DIM + nbJ;
#pragma unroll
                for (int nf = 0; nf < 4; nf++) {
                    const int jj = f.wn * 16 + nf * 4 + f.tg;
                    const float gt = acc[mf][nf][half * 2 + 0];
                    const float up = acc[mf][nf][half * 2 + 1];
                    dst[jj] = up * gt / (1.f + expf(-gt));
                }
            }
        }
    }
}

// ============================================================
// GEMM2 + weighted atomic scatter. grid = (MAXTILES, H/128), 256 thr
// ============================================================
__global__ __launch_bounds__(NTHREADS)
void gemm2_mma(const float* __restrict__ w2, float* __restrict__ out) {
    const int tile_m = blockIdx.x;
    if (tile_m >= g_num_tiles) return;
    const int e     = g_tile_expert[tile_m];
    const int nbase = blockIdx.y * BN;

    extern __shared__ float sm[];

    const int tid = threadIdx.x;
    const int wid = tid >> 5, lid = tid & 31;
    FragCtx f = { wid & 1, wid >> 1, lid >> 2, lid & 3 };

    const int ra  = tid >> 2;
    const int aSb = (tid & 3) * 2;
    const float* aSrc = g_act + (size_t)(tile_m * BM + ra) * I_DIM;   // pad rows stay 0
    const int rb  = tid >> 1;
    const int bSb = (tid & 1) * 4;
    const float* bSrc = w2 + ((size_t)e * H_DIM + (nbase + rb)) * I_DIM;

    const uint32_t smBase = smem_u32(sm);
    uint32_t aDst[NSTAGE], bDst[NSTAGE];
#pragma unroll
    for (int s = 0; s < NSTAGE; s++) {
        aDst[s] = smBase + (s * STAGE_WORDS + ra * SM_STRIDE) * 4 + aSb * 16;
        bDst[s] = smBase + (s * STAGE_WORDS + A_WORDS + rb * SM_STRIDE) * 4 + bSb * 16;
    }

    float acc[2][4][4];
#pragma unroll
    for (int a = 0; a < 2; a++)
#pragma unroll
        for (int b = 0; b < 4; b++)
#pragma unroll
            for (int c = 0; c < 4; c++) acc[a][b][c] = 0.f;

    const int NC = I_DIM / BK;   // 44
    issue_chunk(aDst[0], bDst[0], aSrc, bSrc, 0, aSb, bSb);
    issue_chunk(aDst[1], bDst[1], aSrc, bSrc, BK, aSb, bSb);

    int stage = 0, stage2 = 2;
#pragma unroll 1
    for (int c = 0; c < NC; c++) {
        if (c + 1 < NC) CP_WAIT(1); else CP_WAIT(0);
        __syncthreads();
        if (c + 2 < NC)
            issue_chunk(aDst[stage2], bDst[stage2], aSrc, bSrc, (c + 2) * BK, aSb, bSb);
        mma_chunk(sm + stage * STAGE_WORDS, sm + stage * STAGE_WORDS + A_WORDS, f, acc);
        stage = (stage + 1 == NSTAGE) ? 0 : stage + 1;
        stage2 = (stage2 + 1 == NSTAGE) ? 0 : stage2 + 1;
    }

#pragma unroll
    for (int mf = 0; mf < 2; mf++) {
#pragma unroll
        for (int half = 0; half < 2; half++) {
            const int slot = tile_m * BM + f.wm * 32 + mf * 16 + f.g + half * 8;
            const int tok  = g_token_of_slot[slot];
            if (tok >= 0) {
                const float w = g_slot_weight[slot];
                float* dst = out + (size_t)tok * H_DIM + nbase;
#pragma unroll
                for (int nf = 0; nf < 4; nf++) {
                    const int col = f.wn * 32 + nf * 8 + f.tg * 2;
                    atomicAdd(&dst[col],     w * acc[mf][nf][half * 2 + 0]);
                    atomicAdd(&dst[col + 1], w * acc[mf][nf][half * 2 + 1]);
                }
            }
        }
    }
}

// ============================================================
extern "C" void kernel_launch(void* const* d_in, const int* in_sizes, int n_in,
                              void* d_out, int out_size) {
    const float* x      = (const float*)d_in[0];   // [1024, 2048]
    const float* logits = (const float*)d_in[1];   // [1024, 8]
    const float* w13    = (const float*)d_in[2];   // [8, 2816, 2048]
    const float* w2     = (const float*)d_in[3];   // [8, 2048, 1408]
    float* out = (float*)d_out;                    // [1024, 2048]
    (void)in_sizes; (void)n_in;

    cudaFuncSetAttribute(gemm1_mma, cudaFuncAttributeMaxDynamicSharedMemorySize, SMEM_DYN_BYTES);
    cudaFuncSetAttribute(gemm2_mma, cudaFuncAttributeMaxDynamicSharedMemorySize, SMEM_DYN_BYTES);

    // 3 alignment dummies so ncu (-s 5 -c 1) captures gemm1_mma, not routing.
    dummy_align_kernel<<<1, 32>>>();
    dummy_align_kernel<<<1, 32>>>();
    dummy_align_kernel<<<1, 32>>>();
    cudaMemsetAsync(d_out, 0, (size_t)out_size * sizeof(float));
    routing_kernel<<<1, 1024>>>(logits);
    gemm1_mma<<<dim3(MAXTILES, I_DIM / 64), NTHREADS, SMEM_DYN_BYTES>>>(x, w13);
    gemm2_mma<<<dim3(MAXTILES, H_DIM / BN), NTHREADS, SMEM_DYN_BYTES>>>(w2, out);
}

// round 9
// speedup vs baseline: 1.0298x; 1.0298x over previous
#include <cuda_runtime.h>
#include <cstdint>
#include <math.h>

// ---------------- problem constants ----------------
#define T_TOK 1024
#define H_DIM 2048
#define I_DIM 1408
#define N_EXP 8

// ---------------- tiling (round-7 proven config) ----------------
#define BM 128
#define BN 128
#define BK 32
#define NSTAGE 3
#define MAXSLOT  3072
#define MAXTILES 24
#define NTHREADS 512

#define SM_STRIDE 36      // floats per smem row (144 B)
#define TILE_WORDS (BM * SM_STRIDE)                     // 4608 floats = 18 KB
#define SMEM_DYN_BYTES (2 * NSTAGE * TILE_WORDS * 4)    // 3 stages x (A+B) = 108 KB

// ---------------- scratch ----------------
__device__ int   g_token_of_slot[MAXSLOT];
__device__ float g_slot_weight[MAXSLOT];
__device__ int   g_tile_expert[MAXTILES];
__device__ int   g_num_tiles;
__device__ float g_act[(size_t)MAXSLOT * I_DIM];   // ~17.3 MB

// ---------------- PTX helpers (baseline sm_80+; nothing 'a'-gated) ----------------
__device__ __forceinline__ uint32_t smem_u32(const void* p) {
    uint32_t a;
    asm("{ .reg .u64 t; cvta.to.shared.u64 t, %1; cvt.u32.u64 %0, t; }" : "=r"(a) : "l"(p));
    return a;
}
#define CP_ASYNC16(dst_u32, src_ptr) \
    asm volatile("cp.async.cg.shared.global [%0], [%1], 16;" :: "r"(dst_u32), "l"(src_ptr))
#define CP_COMMIT()  asm volatile("cp.async.commit_group;" ::: "memory")
#define CP_WAIT(N)   asm volatile("cp.async.wait_group %0;" :: "n"(N) : "memory")

// pack two fp32 -> one f16x2 reg. First asm source fills the HIGH half.
// (If hi/lo were ever swapped, A and B swap identically within each k-pair,
//  so the mma dot-product is unchanged — order is self-consistent.)
__device__ __forceinline__ uint32_t packh2(float lo, float hi) {
    uint32_t r;
    asm("cvt.rn.f16x2.f32 %0, %1, %2;" : "=r"(r) : "f"(hi), "f"(lo));
    return r;
}
__device__ __forceinline__ void mma_f16(float* c, const uint32_t* a, const uint32_t* b) {
    asm volatile(
        "mma.sync.aligned.m16n8k16.row.col.f32.f16.f16.f32 "
        "{%0,%1,%2,%3}, {%4,%5,%6,%7}, {%8,%9}, {%0,%1,%2,%3};"
        : "+f"(c[0]), "+f"(c[1]), "+f"(c[2]), "+f"(c[3])
        : "r"(a[0]), "r"(a[1]), "r"(a[2]), "r"(a[3]), "r"(b[0]), "r"(b[1]));
}

// ============================================================
// Routing: softmax -> top2 -> renormalize; padded per-expert slot lists (x128).
// ============================================================
__global__ void routing_kernel(const float* __restrict__ logits) {
    __shared__ int s_cnt[N_EXP];
    __shared__ int s_cur[N_EXP];
    __shared__ int s_off[N_EXP + 1];

    const int t = threadIdx.x;
    if (t < N_EXP) { s_cnt[t] = 0; s_cur[t] = 0; }
    for (int s = t; s < MAXSLOT; s += blockDim.x) g_token_of_slot[s] = -1;
    __syncthreads();

    int e1 = 0, e2 = 0;
    float w1 = 0.f, w2 = 0.f;
    if (t < T_TOK) {
        float l[N_EXP];
#pragma unroll
        for (int e = 0; e < N_EXP; e++) l[e] = logits[t * N_EXP + e];
        float b1 = -1e30f;
#pragma unroll
        for (int e = 0; e < N_EXP; e++) if (l[e] > b1) { b1 = l[e]; e1 = e; }
        float b2 = -1e30f;
        e2 = (e1 == 0) ? 1 : 0;
#pragma unroll
        for (int e = 0; e < N_EXP; e++) if (e != e1 && l[e] > b2) { b2 = l[e]; e2 = e; }
        float p2 = expf(b2 - b1);
        w1 = 1.f / (1.f + p2);
        w2 = p2 / (1.f + p2);
        atomicAdd(&s_cnt[e1], 1);
        atomicAdd(&s_cnt[e2], 1);
    }
    __syncthreads();

    if (t == 0) {
        int off = 0;
        for (int e = 0; e < N_EXP; e++) {
            s_off[e] = off;
            int tiles = (s_cnt[e] + BM - 1) / BM;
            for (int i = 0; i < tiles; i++) g_tile_expert[off / BM + i] = e;
            off += tiles * BM;
        }
        s_off[N_EXP] = off;
        g_num_tiles = off / BM;
    }
    __syncthreads();

    if (t < T_TOK) {
        int p = atomicAdd(&s_cur[e1], 1);
        int s = s_off[e1] + p;
        g_token_of_slot[s] = t;
        g_slot_weight[s]   = w1;
        p = atomicAdd(&s_cur[e2], 1);
        s = s_off[e2] + p;
        g_token_of_slot[s] = t;
        g_slot_weight[s]   = w2;
    }
}

// ============================================================
// Fragment context + per-chunk MMA (fp16 m16n8k16, fp32 accum).
// 16 warps: wm = wid&3 (m-group of 32 rows), wn = wid>>2 (n-group of 32 cols).
// Warp tile 32x32: mf 0..1 (16 rows), nf 0..3 (8 cols). acc[2][4][4].
// Chunk k32 = 2 k16-steps.
// ============================================================
struct FragCtx { int wm, wn, g, tg; };

__device__ __forceinline__ void mma_chunk(const float* __restrict__ A,
                                          const float* __restrict__ B,
                                          const FragCtx& f,
                                          float acc[2][4][4]) {
#pragma unroll
    for (int ks = 0; ks < 2; ks++) {            // two k16 steps
        const int k0 = ks * 16;
        uint32_t af[2][4];
#pragma unroll
        for (int mf = 0; mf < 2; mf++) {
            const int row = f.wm * 32 + mf * 16 + f.g;
            const float* p0 = A + row * SM_STRIDE + k0 + f.tg * 2;           // (row, k)
            const float* p1 = A + (row + 8) * SM_STRIDE + k0 + f.tg * 2;     // (row+8, k)
            float2 v0 = *(const float2*)p0;        // k, k+1
            float2 v1 = *(const float2*)p1;
            float2 v2 = *(const float2*)(p0 + 8);  // k+8, k+9
            float2 v3 = *(const float2*)(p1 + 8);
            af[mf][0] = packh2(v0.x, v0.y);
            af[mf][1] = packh2(v1.x, v1.y);
            af[mf][2] = packh2(v2.x, v2.y);
            af[mf][3] = packh2(v3.x, v3.y);
        }
        uint32_t bf[4][2];
#pragma unroll
        for (int nf = 0; nf < 4; nf++) {
            const int n = f.wn * 32 + nf * 8 + f.g;
            const float* p = B + n * SM_STRIDE + k0 + f.tg * 2;
            float2 v0 = *(const float2*)p;
            float2 v1 = *(const float2*)(p + 8);
            bf[nf][0] = packh2(v0.x, v0.y);
            bf[nf][1] = packh2(v1.x, v1.y);
        }
#pragma unroll
        for (int mf = 0; mf < 2; mf++)
#pragma unroll
            for (int nf = 0; nf < 4; nf++)
                mma_f16(acc[mf][nf], af[mf], bf[nf]);
    }
}

// per-thread loads: 2x16B A + 2x16B B (512 threads cover 128 rows x 8 segs each)
__device__ __forceinline__ void issue_chunk(uint32_t aDst, uint32_t bDst,
                                            const float* aSrc, const float* bSrc,
                                            int kOff, int sb) {
#pragma unroll
    for (int i = 0; i < 2; i++) {
        CP_ASYNC16(aDst + i * 16, aSrc + kOff + (sb + i) * 4);
        CP_ASYNC16(bDst + i * 16, bSrc + kOff + (sb + i) * 4);
    }
    CP_COMMIT();
}

// ============================================================
// GEMM1 + SiLU*up. B rows interleaved gate/up. grid = (MAXTILES, I/64), 512 thr
// ============================================================
__global__ __launch_bounds__(NTHREADS)
void gemm1_mma(const float* __restrict__ x, const float* __restrict__ w13) {
    const int tile_m = blockIdx.x;
    if (tile_m >= g_num_tiles) return;
    const int e   = g_tile_expert[tile_m];
    const int nbJ = blockIdx.y * 64;

    extern __shared__ float sm[];

    const int tid = threadIdx.x;
    const int wid = tid >> 5, lid = tid & 31;
    FragCtx f = { wid & 3, wid >> 2, lid >> 2, lid & 3 };

    const int r  = tid >> 2;            // 0..127
    const int sb = (tid & 3) * 2;       // seg pairs 0,2,4,6
    const int tokr = g_token_of_slot[tile_m * BM + r];
    const float* aSrc = x + (size_t)(tokr < 0 ? 0 : tokr) * H_DIM;
    const int j = r >> 1;
    const int wrow = (r & 1) ? (I_DIM + nbJ + j) : (nbJ + j);
    const float* bSrc = w13 + ((size_t)e * 2 * I_DIM + wrow) * H_DIM;

    const uint32_t smBase = smem_u32(sm);
    const uint32_t thrOff = r * (SM_STRIDE * 4) + sb * 16;
    uint32_t aDst[NSTAGE], bDst[NSTAGE];
#pragma unroll
    for (int s = 0; s < NSTAGE; s++) {
        aDst[s] = smBase + s * (TILE_WORDS * 4) + thrOff;
        bDst[s] = smBase + (NSTAGE + s) * (TILE_WORDS * 4) + thrOff;
    }

    float acc[2][4][4];
#pragma unroll
    for (int a = 0; a < 2; a++)
#pragma unroll
        for (int b = 0; b < 4; b++)
#pragma unroll
            for (int c = 0; c < 4; c++) acc[a][b][c] = 0.f;

    const int NC = H_DIM / BK;   // 64
    issue_chunk(aDst[0], bDst[0], aSrc, bSrc, 0, sb);
    issue_chunk(aDst[1], bDst[1], aSrc, bSrc, BK, sb);

    int stage = 0, stage2 = 2;
#pragma unroll 1
    for (int c = 0; c < NC; c++) {
        if (c + 1 < NC) CP_WAIT(1); else CP_WAIT(0);
        __syncthreads();
        if (c + 2 < NC)
            issue_chunk(aDst[stage2], bDst[stage2], aSrc, bSrc, (c + 2) * BK, sb);
        mma_chunk(sm + stage * TILE_WORDS, sm + (NSTAGE + stage) * TILE_WORDS, f, acc);
        stage = (stage + 1 == NSTAGE) ? 0 : stage + 1;
        stage2 = (stage2 + 1 == NSTAGE) ? 0 : stage2 + 1;
    }

    // epilogue: silu(gate)*up; c-pair (even,odd) = (gate, up) of same col
#pragma unroll
    for (int mf = 0; mf < 2; mf++) {
#pragma unroll
        for (int half = 0; half < 2; half++) {
            const int slot = tile_m * BM + f.wm * 32 + mf * 16 + f.g + half * 8;
            if (g_token_of_slot[slot] >= 0) {
                float* dst = g_act + (size_t)slot * I_DIM + nbJ;
#pragma unroll
                for (int nf = 0; nf < 4; nf++) {
                    const int jj = f.wn * 16 + nf * 4 + f.tg;
                    const float gt = acc[mf][nf][half * 2 + 0];
                    const float up = acc[mf][nf][half * 2 + 1];
                    dst[jj] = up * gt / (1.f + expf(-gt));
                }
            }
        }
    }
}

// ============================================================
// GEMM2 + weighted atomic scatter. grid = (MAXTILES, H/128), 512 thr
// ============================================================
__global__ __launch_bounds__(NTHREADS)
void gemm2_mma(const float* __restrict__ w2, float* __restrict__ out) {
    const int tile_m = blockIdx.x;
    if (tile_m >= g_num_tiles) return;
    const int e     = g_tile_expert[tile_m];
    const int nbase = blockIdx.y * BN;

    extern __shared__ float sm[];

    const int tid = threadIdx.x;
    const int wid = tid >> 5, lid = tid & 31;
    FragCtx f = { wid & 3, wid >> 2, lid >> 2, lid & 3 };

    const int r  = tid >> 2;
    const int sb = (tid & 3) * 2;
    const float* aSrc = g_act + (size_t)(tile_m * BM + r) * I_DIM;   // pad rows stay 0
    const float* bSrc = w2 + ((size_t)e * H_DIM + (nbase + r)) * I_DIM;

    const uint32_t smBase = smem_u32(sm);
    const uint32_t thrOff = r * (SM_STRIDE * 4) + sb * 16;
    uint32_t aDst[NSTAGE], bDst[NSTAGE];
#pragma unroll
    for (int s = 0; s < NSTAGE; s++) {
        aDst[s] = smBase + s * (TILE_WORDS * 4) + thrOff;
        bDst[s] = smBase + (NSTAGE + s) * (TILE_WORDS * 4) + thrOff;
    }

    float acc[2][4][4];
#pragma unroll
    for (int a = 0; a < 2; a++)
#pragma unroll
        for (int b = 0; b < 4; b++)
#pragma unroll
            for (int c = 0; c < 4; c++) acc[a][b][c] = 0.f;

    const int NC = I_DIM / BK;   // 44
    issue_chunk(aDst[0], bDst[0], aSrc, bSrc, 0, sb);
    issue_chunk(aDst[1], bDst[1], aSrc, bSrc, BK, sb);

    int stage = 0, stage2 = 2;
#pragma unroll 1
    for (int c = 0; c < NC; c++) {
        if (c + 1 < NC) CP_WAIT(1); else CP_WAIT(0);
        __syncthreads();
        if (c + 2 < NC)
            issue_chunk(aDst[stage2], bDst[stage2], aSrc, bSrc, (c + 2) * BK, sb);
        mma_chunk(sm + stage * TILE_WORDS, sm + (NSTAGE + stage) * TILE_WORDS, f, acc);
        stage = (stage + 1 == NSTAGE) ? 0 : stage + 1;
        stage2 = (stage2 + 1 == NSTAGE) ? 0 : stage2 + 1;
    }

#pragma unroll
    for (int mf = 0; mf < 2; mf++) {
#pragma unroll
        for (int half = 0; half < 2; half++) {
            const int slot = tile_m * BM + f.wm * 32 + mf * 16 + f.g + half * 8;
            const int tok  = g_token_of_slot[slot];
            if (tok >= 0) {
                const float w = g_slot_weight[slot];
                float* dst = out + (size_t)tok * H_DIM + nbase;
#pragma unroll
                for (int nf = 0; nf < 4; nf++) {
                    const int col = f.wn * 32 + nf * 8 + f.tg * 2;
                    atomicAdd(&dst[col],     w * acc[mf][nf][half * 2 + 0]);
                    atomicAdd(&dst[col + 1], w * acc[mf][nf][half * 2 + 1]);
                }
            }
        }
    }
}

// ============================================================
extern "C" void kernel_launch(void* const* d_in, const int* in_sizes, int n_in,
                              void* d_out, int out_size) {
    const float* x      = (const float*)d_in[0];   // [1024, 2048]
    const float* logits = (const float*)d_in[1];   // [1024, 8]
    const float* w13    = (const float*)d_in[2];   // [8, 2816, 2048]
    const float* w2     = (const float*)d_in[3];   // [8, 2048, 1408]
    float* out = (float*)d_out;                    // [1024, 2048]
    (void)in_sizes; (void)n_in;

    cudaFuncSetAttribute(gemm1_mma, cudaFuncAttributeMaxDynamicSharedMemorySize, SMEM_DYN_BYTES);
    cudaFuncSetAttribute(gemm2_mma, cudaFuncAttributeMaxDynamicSharedMemorySize, SMEM_DYN_BYTES);

    cudaMemsetAsync(d_out, 0, (size_t)out_size * sizeof(float));
    routing_kernel<<<1, 1024>>>(logits);
    gemm1_mma<<<dim3(MAXTILES, I_DIM / 64), NTHREADS, SMEM_DYN_BYTES>>>(x, w13);
    gemm2_mma<<<dim3(MAXTILES, H_DIM / BN), NTHREADS, SMEM_DYN_BYTES>>>(w2, out);
}